// round 1
// baseline (speedup 1.0000x reference)
#include <cuda_runtime.h>
#include <math.h>

// Problem constants
#define BATCH 4
#define SEQ 4096
#define DIM 1024
#define HEADS 16
#define HEAD_DIM 64
#define WIN 128
#define NWIN (SEQ / WIN)      // 32
#define HIDDEN 2048
#define ROWS (BATCH * SEQ)    // 16384
#define LN_EPS 1e-5f

// ---------------------------------------------------------------------------
// Scratch buffers (static __device__ arrays: no allocation in kernel_launch)
// ---------------------------------------------------------------------------
__device__ float g_ln[ROWS * DIM];                       // 64 MB (ln out / attn out, reused)
__device__ float g_q[ROWS * DIM];                        // 64 MB
__device__ float g_k[ROWS * DIM];                        // 64 MB
__device__ float g_v[ROWS * DIM];                        // 64 MB
__device__ float g_x1[ROWS * DIM];                       // 64 MB (post-attn residual stream)
__device__ float g_proj[ROWS * 2 * HIDDEN];              // 256 MB (FF1 output)
__device__ float g_hbuf[ROWS * HIDDEN];                  // 128 MB (geglu output)

// ---------------------------------------------------------------------------
// LayerNorm: one block per row, 256 threads, D=1024 (4 floats/thread)
// ---------------------------------------------------------------------------
__global__ __launch_bounds__(256) void ln_kernel(
    const float* __restrict__ in, const float* __restrict__ gamma,
    const float* __restrict__ beta, float* __restrict__ out)
{
    int row = blockIdx.x;
    const float4* inr = (const float4*)(in + (size_t)row * DIM);
    float4 xv = inr[threadIdx.x];

    float s  = xv.x + xv.y + xv.z + xv.w;
    float ss = xv.x * xv.x + xv.y * xv.y + xv.z * xv.z + xv.w * xv.w;

    // warp reduce
    #pragma unroll
    for (int o = 16; o > 0; o >>= 1) {
        s  += __shfl_down_sync(0xffffffff, s,  o);
        ss += __shfl_down_sync(0xffffffff, ss, o);
    }
    __shared__ float rs[8], rss[8];
    __shared__ float s_mean, s_rstd;
    int warp = threadIdx.x >> 5, lane = threadIdx.x & 31;
    if (lane == 0) { rs[warp] = s; rss[warp] = ss; }
    __syncthreads();
    if (threadIdx.x == 0) {
        float t = 0.f, t2 = 0.f;
        #pragma unroll
        for (int i = 0; i < 8; i++) { t += rs[i]; t2 += rss[i]; }
        float m = t / (float)DIM;
        float var = t2 / (float)DIM - m * m;
        s_mean = m;
        s_rstd = rsqrtf(var + LN_EPS);
    }
    __syncthreads();
    float m = s_mean, r = s_rstd;

    float4 gv = ((const float4*)gamma)[threadIdx.x];
    float4 bv = ((const float4*)beta)[threadIdx.x];
    float4 o;
    o.x = (xv.x - m) * r * gv.x + bv.x;
    o.y = (xv.y - m) * r * gv.y + bv.y;
    o.z = (xv.z - m) * r * gv.z + bv.z;
    o.w = (xv.w - m) * r * gv.w + bv.w;
    ((float4*)(out + (size_t)row * DIM))[threadIdx.x] = o;
}

// ---------------------------------------------------------------------------
// SGEMM: C[M,N] = A[M,K] @ B[K,N]  (+ bias[n])  (+ res[m,n])
// 128x128 tile, BK=8, 256 threads, 8x8 per-thread microtile
// EPI: 0 = none, 1 = +bias, 2 = +bias +res
// ---------------------------------------------------------------------------
template <int EPI>
__global__ __launch_bounds__(256) void sgemm_k(
    const float* __restrict__ A, const float* __restrict__ B,
    const float* __restrict__ bias, const float* __restrict__ res,
    float* __restrict__ C, int M, int N, int K)
{
    const int BM = 128, BN = 128, BK = 8, TM = 8, TN = 8;
    __shared__ float As[BK][BM];
    __shared__ float Bs[BK][BN];

    int tid  = threadIdx.x;
    int row0 = blockIdx.y * BM;
    int col0 = blockIdx.x * BN;

    int arow = tid >> 1,  acol = (tid & 1) * 4;   // A tile: 128 rows x 8 k, 2 thr/row
    int brow = tid >> 5,  bcol = (tid & 31) * 4;  // B tile: 8 k-rows x 128 cols

    const float* Aptr = A + (size_t)(row0 + arow) * K + acol;
    const float* Bptr = B + (size_t)brow * N + col0 + bcol;

    int tr = (tid >> 4) * TM;
    int tc = (tid & 15) * TN;

    float acc[TM][TN];
    #pragma unroll
    for (int i = 0; i < TM; i++)
        #pragma unroll
        for (int j = 0; j < TN; j++) acc[i][j] = 0.f;

    for (int k0 = 0; k0 < K; k0 += BK) {
        float4 av = *(const float4*)Aptr;  Aptr += BK;
        float4 bv = *(const float4*)Bptr;  Bptr += (size_t)BK * N;
        __syncthreads();
        As[acol + 0][arow] = av.x;
        As[acol + 1][arow] = av.y;
        As[acol + 2][arow] = av.z;
        As[acol + 3][arow] = av.w;
        *(float4*)&Bs[brow][bcol] = bv;
        __syncthreads();

        #pragma unroll
        for (int kk = 0; kk < BK; kk++) {
            float ra[TM], rb[TN];
            #pragma unroll
            for (int i = 0; i < TM; i++) ra[i] = As[kk][tr + i];
            #pragma unroll
            for (int j = 0; j < TN; j++) rb[j] = Bs[kk][tc + j];
            #pragma unroll
            for (int i = 0; i < TM; i++)
                #pragma unroll
                for (int j = 0; j < TN; j++)
                    acc[i][j] = fmaf(ra[i], rb[j], acc[i][j]);
        }
    }

    #pragma unroll
    for (int i = 0; i < TM; i++) {
        int r = row0 + tr + i;
        #pragma unroll
        for (int j = 0; j < TN; j += 4) {
            int c = col0 + tc + j;
            float4 v;
            v.x = acc[i][j + 0];
            v.y = acc[i][j + 1];
            v.z = acc[i][j + 2];
            v.w = acc[i][j + 3];
            if (EPI >= 1) {
                v.x += bias[c + 0]; v.y += bias[c + 1];
                v.z += bias[c + 2]; v.w += bias[c + 3];
            }
            if (EPI == 2) {
                float4 rv = *(const float4*)(res + (size_t)r * N + c);
                v.x += rv.x; v.y += rv.y; v.z += rv.z; v.w += rv.w;
            }
            *(float4*)(C + (size_t)r * N + c) = v;
        }
    }
}

// ---------------------------------------------------------------------------
// Sliding-window causal local attention.
// grid = (NWIN, HEADS, BATCH), block = 128 threads (one thread per query row).
// For window n, keys/values come from global positions (n-1)*128 .. (n+1)*128.
// Online (flash) softmax; K/V staged in smem in 64-row chunks (32 KB total).
// Masked entries (dist<0 or first-window left half) are simply skipped.
// ---------------------------------------------------------------------------
#define ACHUNK 64
__global__ __launch_bounds__(128) void attn_kernel(
    const float* __restrict__ Q, const float* __restrict__ K,
    const float* __restrict__ V, const float* __restrict__ relb,
    float* __restrict__ O)
{
    __shared__ float sK[ACHUNK][HEAD_DIM];
    __shared__ float sV[ACHUNK][HEAD_DIM];

    int n = blockIdx.x, h = blockIdx.y, b = blockIdx.z;
    int i = threadIdx.x;  // query row within window, 0..127

    size_t base = (size_t)b * SEQ * DIM + (size_t)h * HEAD_DIM;

    // load this thread's q row into registers (16 float4 loads)
    float q[HEAD_DIM];
    {
        const float4* qp = (const float4*)(Q + base + (size_t)(n * WIN + i) * DIM);
        #pragma unroll
        for (int c = 0; c < HEAD_DIM / 4; c++) {
            float4 t = qp[c];
            q[4 * c + 0] = t.x; q[4 * c + 1] = t.y;
            q[4 * c + 2] = t.z; q[4 * c + 3] = t.w;
        }
    }

    float mmax = -1e30f, lsum = 0.f;
    float acc[HEAD_DIM];
    #pragma unroll
    for (int d = 0; d < HEAD_DIM; d++) acc[d] = 0.f;

    const float* biasrow = relb + h * (2 * WIN);

    for (int c = 0; c < 2 * WIN / ACHUNK; c++) {
        if (n == 0 && c < WIN / ACHUNK) continue;   // first window: left half fully masked (uniform)
        int j0 = c * ACHUNK;
        int pos0 = (n - 1) * WIN + j0;              // global key position of chunk start

        __syncthreads();
        // cooperative load: ACHUNK rows x 16 float4 = 1024 float4 / 128 threads
        for (int t = i; t < ACHUNK * (HEAD_DIM / 4); t += 128) {
            int r = t >> 4, cc = t & 15;
            size_t off = base + (size_t)(pos0 + r) * DIM + cc * 4;
            ((float4*)sK[r])[cc] = *(const float4*)(K + off);
            ((float4*)sV[r])[cc] = *(const float4*)(V + off);
        }
        __syncthreads();

        // causal: j <= i + WIN  ->  jj < i + WIN - j0 + 1
        int jmax = i + WIN - j0 + 1;
        if (jmax > ACHUNK) jmax = ACHUNK;
        for (int jj = 0; jj < jmax; jj++) {
            float s = 0.f;
            #pragma unroll
            for (int d = 0; d < HEAD_DIM; d++) s = fmaf(q[d], sK[jj][d], s);
            int dist = i + WIN - (j0 + jj);         // in [0, 255] for all valid entries
            s = s * 0.125f + biasrow[dist];

            float mnew = fmaxf(mmax, s);
            float cf = __expf(mmax - mnew);
            float p  = __expf(s - mnew);
            lsum = lsum * cf + p;
            #pragma unroll
            for (int d = 0; d < HEAD_DIM; d++)
                acc[d] = fmaf(p, sV[jj][d], acc[d] * cf);
            mmax = mnew;
        }
    }

    float inv = 1.f / lsum;
    float* op = O + base + (size_t)(n * WIN + i) * DIM;
    #pragma unroll
    for (int c = 0; c < HEAD_DIM / 4; c++) {
        float4 t;
        t.x = acc[4 * c + 0] * inv; t.y = acc[4 * c + 1] * inv;
        t.z = acc[4 * c + 2] * inv; t.w = acc[4 * c + 3] * inv;
        *(float4*)(op + 4 * c) = t;
    }
}

// ---------------------------------------------------------------------------
// GEGLU: h[m, j] = proj[m, j] * gelu_exact(proj[m, HIDDEN + j])
// ---------------------------------------------------------------------------
__global__ __launch_bounds__(256) void geglu_kernel(
    const float* __restrict__ proj, float* __restrict__ h)
{
    int t = blockIdx.x * blockDim.x + threadIdx.x;   // over ROWS*HIDDEN
    int r = t / HIDDEN, c = t - r * HIDDEN;
    float val  = proj[(size_t)r * (2 * HIDDEN) + c];
    float gate = proj[(size_t)r * (2 * HIDDEN) + HIDDEN + c];
    float ge = 0.5f * gate * (1.f + erff(gate * 0.70710678118654752440f));
    h[t] = val * ge;
}

// ---------------------------------------------------------------------------
// Launch
// ---------------------------------------------------------------------------
extern "C" void kernel_launch(void* const* d_in, const int* in_sizes, int n_in,
                              void* d_out, int out_size)
{
    const float* x      = (const float*)d_in[0];
    const float* ln1_g  = (const float*)d_in[1];
    const float* ln1_b  = (const float*)d_in[2];
    const float* ln2_g  = (const float*)d_in[3];
    const float* ln2_b  = (const float*)d_in[4];
    const float* wq     = (const float*)d_in[5];
    const float* wk     = (const float*)d_in[6];
    const float* wv     = (const float*)d_in[7];
    const float* wo     = (const float*)d_in[8];
    const float* bo     = (const float*)d_in[9];
    const float* relb   = (const float*)d_in[10];
    const float* w_ff1  = (const float*)d_in[11];
    const float* b_ff1  = (const float*)d_in[12];
    const float* w_ff2  = (const float*)d_in[13];
    const float* b_ff2  = (const float*)d_in[14];
    float* out = (float*)d_out;

    float *ln, *q, *k, *v, *x1, *proj, *hbuf;
    cudaGetSymbolAddress((void**)&ln,   g_ln);
    cudaGetSymbolAddress((void**)&q,    g_q);
    cudaGetSymbolAddress((void**)&k,    g_k);
    cudaGetSymbolAddress((void**)&v,    g_v);
    cudaGetSymbolAddress((void**)&x1,   g_x1);
    cudaGetSymbolAddress((void**)&proj, g_proj);
    cudaGetSymbolAddress((void**)&hbuf, g_hbuf);

    dim3 gD(DIM / 128, ROWS / 128);          // (8, 128)
    dim3 gF1(2 * HIDDEN / 128, ROWS / 128);  // (32, 128)
    dim3 gA(NWIN, HEADS, BATCH);             // (32, 16, 4)

    // 1. ln1(x) -> ln
    ln_kernel<<<ROWS, 256>>>(x, ln1_g, ln1_b, ln);
    // 2-4. q/k/v projections
    sgemm_k<0><<<gD, 256>>>(ln, wq, nullptr, nullptr, q, ROWS, DIM, DIM);
    sgemm_k<0><<<gD, 256>>>(ln, wk, nullptr, nullptr, k, ROWS, DIM, DIM);
    sgemm_k<0><<<gD, 256>>>(ln, wv, nullptr, nullptr, v, ROWS, DIM, DIM);
    // 5. attention -> ln (buffer reuse)
    attn_kernel<<<gA, 128>>>(q, k, v, relb, ln);
    // 6. x1 = attn @ wo + bo + x
    sgemm_k<2><<<gD, 256>>>(ln, wo, bo, x, x1, ROWS, DIM, DIM);
    // 7. ln2(x1) -> ln
    ln_kernel<<<ROWS, 256>>>(x1, ln2_g, ln2_b, ln);
    // 8. proj = ln @ w_ff1 + b_ff1
    sgemm_k<1><<<gF1, 256>>>(ln, w_ff1, b_ff1, nullptr, proj, ROWS, 2 * HIDDEN, DIM);
    // 9. h = val * gelu(gate)
    geglu_kernel<<<(ROWS * HIDDEN) / 256, 256>>>(proj, hbuf);
    // 10. out = h @ w_ff2 + b_ff2 + x1
    sgemm_k<2><<<gD, 256>>>(hbuf, w_ff2, b_ff2, x1, out, ROWS, DIM, HIDDEN);
}

// round 3
// speedup vs baseline: 1.9696x; 1.9696x over previous
#include <cuda_runtime.h>
#include <cuda_bf16.h>
#include <cstdint>
#include <math.h>

#define BATCH 4
#define SEQ 4096
#define DIM 1024
#define HEADS 16
#define HEAD_DIM 64
#define WIN 128
#define NWIN 32
#define HIDDEN 2048
#define ROWS 16384
#define LN_EPS 1e-5f

// ---------------------------------------------------------------------------
// Scratch buffers
// ---------------------------------------------------------------------------
__device__ __align__(256) __nv_bfloat16 g_ah[(size_t)ROWS * 2048];   // activation hi
__device__ __align__(256) __nv_bfloat16 g_al[(size_t)ROWS * 2048];   // activation lo
__device__ __align__(256) float g_qkv[(size_t)ROWS * 3072];
__device__ __align__(256) float g_x1[(size_t)ROWS * DIM];
__device__ __align__(256) float g_proj[(size_t)ROWS * 4096];
__device__ __align__(256) __nv_bfloat16 g_wqkv_h[3072 * 1024], g_wqkv_l[3072 * 1024];
__device__ __align__(256) __nv_bfloat16 g_wo_h[1024 * 1024],   g_wo_l[1024 * 1024];
__device__ __align__(256) __nv_bfloat16 g_ff1_h[4096 * 1024],  g_ff1_l[4096 * 1024];
__device__ __align__(256) __nv_bfloat16 g_ff2_h[1024 * 2048],  g_ff2_l[1024 * 2048];

// ---------------------------------------------------------------------------
// PTX helpers (baseline sm_80-class PTX only: compiles on compute_103)
// ---------------------------------------------------------------------------
__device__ __forceinline__ uint32_t smem_to_u32(const void* p) {
    uint32_t a;
    asm("{ .reg .u64 t; cvta.to.shared.u64 t, %1; cvt.u32.u64 %0, t; }" : "=r"(a) : "l"(p));
    return a;
}
__device__ __forceinline__ void cp16(uint32_t dst, const void* src) {
    asm volatile("cp.async.cg.shared.global [%0], [%1], 16;" :: "r"(dst), "l"(src));
}
__device__ __forceinline__ void ldsm4(uint32_t* r, uint32_t addr) {
    asm volatile("ldmatrix.sync.aligned.m8n8.x4.shared.b16 {%0,%1,%2,%3}, [%4];"
        : "=r"(r[0]), "=r"(r[1]), "=r"(r[2]), "=r"(r[3]) : "r"(addr));
}
__device__ __forceinline__ void mma16816(float* c, const uint32_t* a, const uint32_t* b) {
    asm volatile(
        "mma.sync.aligned.m16n8k16.row.col.f32.bf16.bf16.f32 "
        "{%0,%1,%2,%3}, {%4,%5,%6,%7}, {%8,%9}, {%0,%1,%2,%3};"
        : "+f"(c[0]), "+f"(c[1]), "+f"(c[2]), "+f"(c[3])
        : "r"(a[0]), "r"(a[1]), "r"(a[2]), "r"(a[3]), "r"(b[0]), "r"(b[1]));
}

// ---------------------------------------------------------------------------
// GEMM: C[M,N] = A @ B^T, A/B fp32 pre-split into bf16 hi/lo.
// 3-product compensation via virtual K' = 3K with segment pointers:
//   seg0: Ah*Bh, seg1: Al*Bh, seg2: Ah*Bl
// BM=BN=128, BK=32, 256 thr, 3-stage cp.async, ldmatrix + mma.sync m16n8k16.
// ---------------------------------------------------------------------------
#define BM 128
#define BN 128
#define BK 32
#define STG_BYTES 16384   // A 8KB + B 8KB per stage
#define NSTAGE 3

template <bool BIAS, bool RES>
__global__ __launch_bounds__(256, 2) void gemm_mma(
    const __nv_bfloat16* __restrict__ Agh, const __nv_bfloat16* __restrict__ Agl,
    const __nv_bfloat16* __restrict__ Bgh, const __nv_bfloat16* __restrict__ Bgl,
    const float* __restrict__ bias, const float* __restrict__ res,
    float* __restrict__ C, int K, int N)
{
    __shared__ __align__(1024) char smem[NSTAGE * STG_BYTES];
    uint32_t sb = smem_to_u32(smem);
    int tid = threadIdx.x, lane = tid & 31, wid = tid >> 5;
    int row0 = blockIdx.y * BM, col0 = blockIdx.x * BN;
    int wm = (wid & 3) * 32, wn = (wid >> 2) * 64;
    int NK = K / BK, total = 3 * NK;

    const __nv_bfloat16* Aseg[3] = {Agh, Agl, Agh};
    const __nv_bfloat16* Bseg[3] = {Bgh, Bgh, Bgl};

    // --- copy geometry: 2 A-chunks + 2 B-chunks of 16B per thread ---
    uint32_t dA[2], dB[2];
    size_t sAo[2], sBo[2];
#pragma unroll
    for (int i = 0; i < 2; i++) {
        int cid = tid + i * 256;
        int r = cid >> 2, c = cid & 3;
        uint32_t off = (uint32_t)(r * 64 + ((c ^ (r & 3)) << 4));
        dA[i] = off;
        dB[i] = 8192u + off;
        sAo[i] = (size_t)(row0 + r) * K + c * 8;
        sBo[i] = (size_t)(col0 + r) * K + c * 8;
    }

    auto load_stage = [&](int kv, int s) {
        int seg = (kv >= 2 * NK) ? 2 : (kv >= NK ? 1 : 0);
        int k0 = (kv - seg * NK) * BK;
        const __nv_bfloat16* A = Aseg[seg] + k0;
        const __nv_bfloat16* B = Bseg[seg] + k0;
        uint32_t st = sb + (uint32_t)s * STG_BYTES;
#pragma unroll
        for (int i = 0; i < 2; i++) {
            cp16(st + dA[i], A + sAo[i]);
            cp16(st + dB[i], B + sBo[i]);
        }
        asm volatile("cp.async.commit_group;" ::: "memory");
    };

    // --- ldmatrix address offsets (within a stage) ---
    uint32_t offA[2][2], offB[2][4];
#pragma unroll
    for (int ks = 0; ks < 2; ks++) {
#pragma unroll
        for (int mt = 0; mt < 2; mt++) {
            int r = wm + mt * 16 + (lane & 15);
            int c = ks * 2 + (lane >> 4);
            offA[ks][mt] = (uint32_t)(r * 64 + ((c ^ (r & 3)) << 4));
        }
#pragma unroll
        for (int nt = 0; nt < 4; nt++) {
            int r = wn + nt * 16 + (lane & 7) + ((lane & 16) >> 1);
            int c = ks * 2 + ((lane >> 3) & 1);
            offB[ks][nt] = (uint32_t)(8192 + r * 64 + ((c ^ (r & 3)) << 4));
        }
    }

    float acc[2][8][4];
#pragma unroll
    for (int mt = 0; mt < 2; mt++)
#pragma unroll
        for (int f = 0; f < 8; f++)
#pragma unroll
            for (int j = 0; j < 4; j++) acc[mt][f][j] = 0.f;

    load_stage(0, 0);
    load_stage(1, 1);

    for (int kv = 0; kv < total; kv++) {
        if (kv < total - 1)
            asm volatile("cp.async.wait_group 1;" ::: "memory");
        else
            asm volatile("cp.async.wait_group 0;" ::: "memory");
        __syncthreads();
        if (kv + 2 < total) load_stage(kv + 2, (kv + 2) % NSTAGE);

        uint32_t st = sb + (uint32_t)(kv % NSTAGE) * STG_BYTES;
#pragma unroll
        for (int ks = 0; ks < 2; ks++) {
            uint32_t a[2][4], b[4][4];
#pragma unroll
            for (int mt = 0; mt < 2; mt++) ldsm4(a[mt], st + offA[ks][mt]);
#pragma unroll
            for (int nt = 0; nt < 4; nt++) ldsm4(b[nt], st + offB[ks][nt]);
#pragma unroll
            for (int mt = 0; mt < 2; mt++)
#pragma unroll
                for (int f = 0; f < 8; f++)
                    mma16816(acc[mt][f], a[mt], &b[f >> 1][(f & 1) * 2]);
        }
    }

    // --- epilogue ---
    int mrow = lane >> 2, ncol = (lane & 3) * 2;
#pragma unroll
    for (int mt = 0; mt < 2; mt++) {
#pragma unroll
        for (int h = 0; h < 2; h++) {
            int row = row0 + wm + mt * 16 + h * 8 + mrow;
            size_t rb = (size_t)row * N;
#pragma unroll
            for (int nt = 0; nt < 8; nt++) {
                int col = col0 + wn + nt * 8 + ncol;
                float2 v;
                v.x = acc[mt][nt][h * 2 + 0];
                v.y = acc[mt][nt][h * 2 + 1];
                if (BIAS) { v.x += bias[col]; v.y += bias[col + 1]; }
                if (RES) {
                    float2 rv = *(const float2*)(res + rb + col);
                    v.x += rv.x; v.y += rv.y;
                }
                *(float2*)(C + rb + col) = v;
            }
        }
    }
}

// ---------------------------------------------------------------------------
// Weight transpose + hi/lo split: W[K,N] fp32 -> T[N,K] bf16 (hi, lo)
// ---------------------------------------------------------------------------
__global__ void wsplit(const float* __restrict__ W, __nv_bfloat16* __restrict__ Th,
                       __nv_bfloat16* __restrict__ Tl, int K, int N, int rowOff)
{
    __shared__ float tile[32][33];
    int n0 = blockIdx.x * 32, k0 = blockIdx.y * 32;
    int tx = threadIdx.x, ty = threadIdx.y;
    for (int j = ty; j < 32; j += 8)
        tile[j][tx] = W[(size_t)(k0 + j) * N + n0 + tx];
    __syncthreads();
    for (int j = ty; j < 32; j += 8) {
        float v = tile[tx][j];
        size_t o = (size_t)(rowOff + n0 + j) * K + k0 + tx;
        __nv_bfloat16 hh = __float2bfloat16(v);
        Th[o] = hh;
        Tl[o] = __float2bfloat16(v - __bfloat162float(hh));
    }
}

// ---------------------------------------------------------------------------
// LayerNorm -> bf16 hi/lo
// ---------------------------------------------------------------------------
__global__ __launch_bounds__(256) void ln_split(
    const float* __restrict__ in, const float* __restrict__ gamma,
    const float* __restrict__ beta, __nv_bfloat16* __restrict__ oh,
    __nv_bfloat16* __restrict__ ol)
{
    int row = blockIdx.x;
    const float4* inr = (const float4*)(in + (size_t)row * DIM);
    float4 xv = inr[threadIdx.x];

    float s  = xv.x + xv.y + xv.z + xv.w;
    float ss = xv.x * xv.x + xv.y * xv.y + xv.z * xv.z + xv.w * xv.w;
#pragma unroll
    for (int o = 16; o > 0; o >>= 1) {
        s  += __shfl_down_sync(0xffffffff, s,  o);
        ss += __shfl_down_sync(0xffffffff, ss, o);
    }
    __shared__ float rs[8], rss[8];
    __shared__ float s_mean, s_rstd;
    int warp = threadIdx.x >> 5, lane = threadIdx.x & 31;
    if (lane == 0) { rs[warp] = s; rss[warp] = ss; }
    __syncthreads();
    if (threadIdx.x == 0) {
        float t = 0.f, t2 = 0.f;
#pragma unroll
        for (int i = 0; i < 8; i++) { t += rs[i]; t2 += rss[i]; }
        float m = t / (float)DIM;
        s_mean = m;
        s_rstd = rsqrtf(t2 / (float)DIM - m * m + LN_EPS);
    }
    __syncthreads();
    float m = s_mean, r = s_rstd;

    float4 gv = ((const float4*)gamma)[threadIdx.x];
    float4 bv = ((const float4*)beta)[threadIdx.x];
    float o0 = (xv.x - m) * r * gv.x + bv.x;
    float o1 = (xv.y - m) * r * gv.y + bv.y;
    float o2 = (xv.z - m) * r * gv.z + bv.z;
    float o3 = (xv.w - m) * r * gv.w + bv.w;

    size_t ob = (size_t)row * DIM + threadIdx.x * 4;
    __nv_bfloat162 h0, h1, l0, l1;
    h0.x = __float2bfloat16(o0); h0.y = __float2bfloat16(o1);
    h1.x = __float2bfloat16(o2); h1.y = __float2bfloat16(o3);
    l0.x = __float2bfloat16(o0 - __bfloat162float(h0.x));
    l0.y = __float2bfloat16(o1 - __bfloat162float(h0.y));
    l1.x = __float2bfloat16(o2 - __bfloat162float(h1.x));
    l1.y = __float2bfloat16(o3 - __bfloat162float(h1.y));
    *(__nv_bfloat162*)(oh + ob)     = h0;
    *(__nv_bfloat162*)(oh + ob + 2) = h1;
    *(__nv_bfloat162*)(ol + ob)     = l0;
    *(__nv_bfloat162*)(ol + ob + 2) = l1;
}

// ---------------------------------------------------------------------------
// Sliding-window causal local attention (reads fused QKV fp32, writes bf16 h/l)
// ---------------------------------------------------------------------------
#define ACHUNK 64
__global__ __launch_bounds__(128) void attn_kernel(
    const float* __restrict__ QKV, const float* __restrict__ relb,
    __nv_bfloat16* __restrict__ Oh, __nv_bfloat16* __restrict__ Ol)
{
    __shared__ float sK[ACHUNK][HEAD_DIM];
    __shared__ float sV[ACHUNK][HEAD_DIM];

    int n = blockIdx.x, h = blockIdx.y, b = blockIdx.z;
    int i = threadIdx.x;

    size_t rowq = (size_t)(b * SEQ + n * WIN + i);
    float q[HEAD_DIM];
    {
        const float4* qp = (const float4*)(QKV + rowq * 3072 + h * HEAD_DIM);
#pragma unroll
        for (int c = 0; c < HEAD_DIM / 4; c++) {
            float4 t = qp[c];
            q[4 * c + 0] = t.x; q[4 * c + 1] = t.y;
            q[4 * c + 2] = t.z; q[4 * c + 3] = t.w;
        }
    }

    float mmax = -1e30f, lsum = 0.f;
    float acc[HEAD_DIM];
#pragma unroll
    for (int d = 0; d < HEAD_DIM; d++) acc[d] = 0.f;

    const float* biasrow = relb + h * (2 * WIN);

    for (int c = 0; c < 2 * WIN / ACHUNK; c++) {
        if (n == 0 && c < WIN / ACHUNK) continue;
        int j0 = c * ACHUNK;
        int pos0 = (n - 1) * WIN + j0;

        __syncthreads();
        for (int t = i; t < ACHUNK * (HEAD_DIM / 4); t += 128) {
            int r = t >> 4, cc = t & 15;
            size_t rk = (size_t)(b * SEQ + pos0 + r) * 3072 + h * HEAD_DIM;
            ((float4*)sK[r])[cc] = *(const float4*)(QKV + rk + 1024 + cc * 4);
            ((float4*)sV[r])[cc] = *(const float4*)(QKV + rk + 2048 + cc * 4);
        }
        __syncthreads();

        int jmax = i + WIN - j0 + 1;
        if (jmax > ACHUNK) jmax = ACHUNK;
        for (int jj = 0; jj < jmax; jj++) {
            float s = 0.f;
#pragma unroll
            for (int d = 0; d < HEAD_DIM; d++) s = fmaf(q[d], sK[jj][d], s);
            int dist = i + WIN - (j0 + jj);
            s = s * 0.125f + biasrow[dist];

            float mnew = fmaxf(mmax, s);
            float cf = __expf(mmax - mnew);
            float p  = __expf(s - mnew);
            lsum = lsum * cf + p;
#pragma unroll
            for (int d = 0; d < HEAD_DIM; d++)
                acc[d] = fmaf(p, sV[jj][d], acc[d] * cf);
            mmax = mnew;
        }
    }

    float inv = 1.f / lsum;
    size_t ob = rowq * DIM + h * HEAD_DIM;
#pragma unroll
    for (int d = 0; d < HEAD_DIM; d += 2) {
        float a0 = acc[d] * inv, a1 = acc[d + 1] * inv;
        __nv_bfloat162 hh, ll;
        hh.x = __float2bfloat16(a0); hh.y = __float2bfloat16(a1);
        ll.x = __float2bfloat16(a0 - __bfloat162float(hh.x));
        ll.y = __float2bfloat16(a1 - __bfloat162float(hh.y));
        *(__nv_bfloat162*)(Oh + ob + d) = hh;
        *(__nv_bfloat162*)(Ol + ob + d) = ll;
    }
}

// ---------------------------------------------------------------------------
// GEGLU -> bf16 hi/lo
// ---------------------------------------------------------------------------
__global__ __launch_bounds__(256) void geglu_split(
    const float* __restrict__ proj, __nv_bfloat16* __restrict__ oh,
    __nv_bfloat16* __restrict__ ol)
{
    size_t t4 = ((size_t)blockIdx.x * 256 + threadIdx.x) * 4;
    size_t row = t4 / HIDDEN;
    int c = (int)(t4 - row * HIDDEN);
    float4 val  = *(const float4*)(proj + row * 4096 + c);
    float4 gate = *(const float4*)(proj + row * 4096 + 2048 + c);

    float o[4];
    float gx[4] = {gate.x, gate.y, gate.z, gate.w};
    float vx[4] = {val.x, val.y, val.z, val.w};
#pragma unroll
    for (int j = 0; j < 4; j++) {
        float ge = 0.5f * gx[j] * (1.f + erff(gx[j] * 0.70710678118654752440f));
        o[j] = vx[j] * ge;
    }
    __nv_bfloat162 h0, h1, l0, l1;
    h0.x = __float2bfloat16(o[0]); h0.y = __float2bfloat16(o[1]);
    h1.x = __float2bfloat16(o[2]); h1.y = __float2bfloat16(o[3]);
    l0.x = __float2bfloat16(o[0] - __bfloat162float(h0.x));
    l0.y = __float2bfloat16(o[1] - __bfloat162float(h0.y));
    l1.x = __float2bfloat16(o[2] - __bfloat162float(h1.x));
    l1.y = __float2bfloat16(o[3] - __bfloat162float(h1.y));
    *(__nv_bfloat162*)(oh + t4)     = h0;
    *(__nv_bfloat162*)(oh + t4 + 2) = h1;
    *(__nv_bfloat162*)(ol + t4)     = l0;
    *(__nv_bfloat162*)(ol + t4 + 2) = l1;
}

// ---------------------------------------------------------------------------
// Launch
// ---------------------------------------------------------------------------
extern "C" void kernel_launch(void* const* d_in, const int* in_sizes, int n_in,
                              void* d_out, int out_size)
{
    const float* x      = (const float*)d_in[0];
    const float* ln1_g  = (const float*)d_in[1];
    const float* ln1_b  = (const float*)d_in[2];
    const float* ln2_g  = (const float*)d_in[3];
    const float* ln2_b  = (const float*)d_in[4];
    const float* wq     = (const float*)d_in[5];
    const float* wk     = (const float*)d_in[6];
    const float* wv     = (const float*)d_in[7];
    const float* wo     = (const float*)d_in[8];
    const float* bo     = (const float*)d_in[9];
    const float* relb   = (const float*)d_in[10];
    const float* w_ff1  = (const float*)d_in[11];
    const float* b_ff1  = (const float*)d_in[12];
    const float* w_ff2  = (const float*)d_in[13];
    const float* b_ff2  = (const float*)d_in[14];
    float* out = (float*)d_out;

    __nv_bfloat16 *ah, *al, *wqkvh, *wqkvl, *woh, *wol, *f1h, *f1l, *f2h, *f2l;
    float *qkv, *x1, *proj;
    cudaGetSymbolAddress((void**)&ah, g_ah);
    cudaGetSymbolAddress((void**)&al, g_al);
    cudaGetSymbolAddress((void**)&qkv, g_qkv);
    cudaGetSymbolAddress((void**)&x1, g_x1);
    cudaGetSymbolAddress((void**)&proj, g_proj);
    cudaGetSymbolAddress((void**)&wqkvh, g_wqkv_h);
    cudaGetSymbolAddress((void**)&wqkvl, g_wqkv_l);
    cudaGetSymbolAddress((void**)&woh, g_wo_h);
    cudaGetSymbolAddress((void**)&wol, g_wo_l);
    cudaGetSymbolAddress((void**)&f1h, g_ff1_h);
    cudaGetSymbolAddress((void**)&f1l, g_ff1_l);
    cudaGetSymbolAddress((void**)&f2h, g_ff2_h);
    cudaGetSymbolAddress((void**)&f2l, g_ff2_l);

    dim3 tb(32, 8);
    wsplit<<<dim3(32, 32), tb>>>(wq,    wqkvh, wqkvl, 1024, 1024, 0);
    wsplit<<<dim3(32, 32), tb>>>(wk,    wqkvh, wqkvl, 1024, 1024, 1024);
    wsplit<<<dim3(32, 32), tb>>>(wv,    wqkvh, wqkvl, 1024, 1024, 2048);
    wsplit<<<dim3(32, 32), tb>>>(wo,    woh,   wol,   1024, 1024, 0);
    wsplit<<<dim3(128, 32), tb>>>(w_ff1, f1h,  f1l,   1024, 4096, 0);
    wsplit<<<dim3(32, 64), tb>>>(w_ff2, f2h,   f2l,   2048, 1024, 0);

    // 1. ln1(x) -> ah/al
    ln_split<<<ROWS, 256>>>(x, ln1_g, ln1_b, ah, al);
    // 2. qkv = ln @ [wq|wk|wv]
    gemm_mma<false, false><<<dim3(3072 / BN, ROWS / BM), 256>>>(
        ah, al, wqkvh, wqkvl, nullptr, nullptr, qkv, 1024, 3072);
    // 3. attention -> ah/al
    attn_kernel<<<dim3(NWIN, HEADS, BATCH), 128>>>(qkv, relb, ah, al);
    // 4. x1 = attn @ wo + bo + x
    gemm_mma<true, true><<<dim3(1024 / BN, ROWS / BM), 256>>>(
        ah, al, woh, wol, bo, x, x1, 1024, 1024);
    // 5. ln2(x1) -> ah/al
    ln_split<<<ROWS, 256>>>(x1, ln2_g, ln2_b, ah, al);
    // 6. proj = ln2 @ w_ff1 + b_ff1
    gemm_mma<true, false><<<dim3(4096 / BN, ROWS / BM), 256>>>(
        ah, al, f1h, f1l, b_ff1, nullptr, proj, 1024, 4096);
    // 7. geglu -> ah/al (as [ROWS, 2048])
    geglu_split<<<(ROWS * HIDDEN) / 1024, 256>>>(proj, ah, al);
    // 8. out = h @ w_ff2 + b_ff2 + x1
    gemm_mma<true, true><<<dim3(1024 / BN, ROWS / BM), 256>>>(
        ah, al, f2h, f2l, b_ff2, x1, out, 2048, 1024);
}

// round 4
// speedup vs baseline: 4.1698x; 2.1171x over previous
#include <cuda_runtime.h>
#include <cuda_fp16.h>
#include <cstdint>
#include <math.h>

#define BATCH 4
#define SEQ 4096
#define DIM 1024
#define HEADS 16
#define HEAD_DIM 64
#define WIN 128
#define NWIN 32
#define HIDDEN 2048
#define ROWS 16384
#define LN_EPS 1e-5f

// ---------------------------------------------------------------------------
// Scratch buffers (fp16 activations / weights, fp32 residual stream)
// ---------------------------------------------------------------------------
__device__ __align__(256) __half g_act[(size_t)ROWS * 2048];    // ln out / attn out / geglu out
__device__ __align__(256) __half g_qkv[(size_t)ROWS * 3072];
__device__ __align__(256) float  g_x1[(size_t)ROWS * DIM];
__device__ __align__(256) __half g_proj[(size_t)ROWS * 4096];
__device__ __align__(256) __half g_wqkv[3072 * 1024];
__device__ __align__(256) __half g_wo[1024 * 1024];
__device__ __align__(256) __half g_ff1[4096 * 1024];
__device__ __align__(256) __half g_ff2[1024 * 2048];

// ---------------------------------------------------------------------------
// PTX helpers (baseline sm_80-class PTX: assembles on compute_103)
// ---------------------------------------------------------------------------
__device__ __forceinline__ uint32_t smem_to_u32(const void* p) {
    uint32_t a;
    asm("{ .reg .u64 t; cvta.to.shared.u64 t, %1; cvt.u32.u64 %0, t; }" : "=r"(a) : "l"(p));
    return a;
}
__device__ __forceinline__ void cp16(uint32_t dst, const void* src) {
    asm volatile("cp.async.cg.shared.global [%0], [%1], 16;" :: "r"(dst), "l"(src));
}
__device__ __forceinline__ void ldsm4(uint32_t* r, uint32_t addr) {
    asm volatile("ldmatrix.sync.aligned.m8n8.x4.shared.b16 {%0,%1,%2,%3}, [%4];"
        : "=r"(r[0]), "=r"(r[1]), "=r"(r[2]), "=r"(r[3]) : "r"(addr));
}
__device__ __forceinline__ void mma16816(float* c, const uint32_t* a, const uint32_t* b) {
    asm volatile(
        "mma.sync.aligned.m16n8k16.row.col.f32.f16.f16.f32 "
        "{%0,%1,%2,%3}, {%4,%5,%6,%7}, {%8,%9}, {%0,%1,%2,%3};"
        : "+f"(c[0]), "+f"(c[1]), "+f"(c[2]), "+f"(c[3])
        : "r"(a[0]), "r"(a[1]), "r"(a[2]), "r"(a[3]), "r"(b[0]), "r"(b[1]));
}

// ---------------------------------------------------------------------------
// GEMM: C[M,N] = A @ B^T, fp16 operands, fp32 accumulate.
// A: [M,K] K-major, B: [N,K] K-major.
// BM=BN=128, BK=32, 256 thr, 4-stage cp.async (dynamic smem), m16n8k16.
// ---------------------------------------------------------------------------
#define BM 128
#define BN 128
#define BK 32
#define STG_BYTES 16384   // A 8KB + B 8KB per stage
#define NSTAGE 4
#define GEMM_SMEM (NSTAGE * STG_BYTES)

template <bool BIAS, bool RES, typename OutT>
__global__ __launch_bounds__(256, 2) void gemm_mma(
    const __half* __restrict__ Ag, const __half* __restrict__ Bg,
    const float* __restrict__ bias, const float* __restrict__ res,
    OutT* __restrict__ C, int K, int N)
{
    extern __shared__ __align__(1024) char smem[];
    uint32_t sb = smem_to_u32(smem);
    int tid = threadIdx.x, lane = tid & 31, wid = tid >> 5;
    int row0 = blockIdx.y * BM, col0 = blockIdx.x * BN;
    int wm = (wid & 3) * 32, wn = (wid >> 2) * 64;
    int total = K / BK;

    // --- copy geometry: 2 A-chunks + 2 B-chunks of 16B per thread ---
    uint32_t dA[2], dB[2];
    size_t sAo[2], sBo[2];
#pragma unroll
    for (int i = 0; i < 2; i++) {
        int cid = tid + i * 256;
        int r = cid >> 2, c = cid & 3;
        uint32_t off = (uint32_t)(r * 64 + ((c ^ (r & 3)) << 4));
        dA[i] = off;
        dB[i] = 8192u + off;
        sAo[i] = (size_t)(row0 + r) * K + c * 8;
        sBo[i] = (size_t)(col0 + r) * K + c * 8;
    }

    auto load_stage = [&](int kv, int s) {
        int k0 = kv * BK;
        uint32_t st = sb + (uint32_t)s * STG_BYTES;
#pragma unroll
        for (int i = 0; i < 2; i++) {
            cp16(st + dA[i], Ag + sAo[i] + k0);
            cp16(st + dB[i], Bg + sBo[i] + k0);
        }
        asm volatile("cp.async.commit_group;" ::: "memory");
    };

    // --- ldmatrix address offsets (within a stage) ---
    uint32_t offA[2][2], offB[2][4];
#pragma unroll
    for (int ks = 0; ks < 2; ks++) {
#pragma unroll
        for (int mt = 0; mt < 2; mt++) {
            int r = wm + mt * 16 + (lane & 15);
            int c = ks * 2 + (lane >> 4);
            offA[ks][mt] = (uint32_t)(r * 64 + ((c ^ (r & 3)) << 4));
        }
#pragma unroll
        for (int nt = 0; nt < 4; nt++) {
            int r = wn + nt * 16 + (lane & 7) + ((lane & 16) >> 1);
            int c = ks * 2 + ((lane >> 3) & 1);
            offB[ks][nt] = (uint32_t)(8192 + r * 64 + ((c ^ (r & 3)) << 4));
        }
    }

    float acc[2][8][4];
#pragma unroll
    for (int mt = 0; mt < 2; mt++)
#pragma unroll
        for (int f = 0; f < 8; f++)
#pragma unroll
            for (int j = 0; j < 4; j++) acc[mt][f][j] = 0.f;

    load_stage(0, 0);
    load_stage(1, 1);
    load_stage(2, 2);

    for (int kv = 0; kv < total; kv++) {
        if (kv < total - 2)
            asm volatile("cp.async.wait_group 2;" ::: "memory");
        else if (kv == total - 2)
            asm volatile("cp.async.wait_group 1;" ::: "memory");
        else
            asm volatile("cp.async.wait_group 0;" ::: "memory");
        __syncthreads();
        if (kv + 3 < total) load_stage(kv + 3, (kv + 3) % NSTAGE);

        uint32_t st = sb + (uint32_t)(kv % NSTAGE) * STG_BYTES;
#pragma unroll
        for (int ks = 0; ks < 2; ks++) {
            uint32_t a[2][4], b[4][4];
#pragma unroll
            for (int mt = 0; mt < 2; mt++) ldsm4(a[mt], st + offA[ks][mt]);
#pragma unroll
            for (int nt = 0; nt < 4; nt++) ldsm4(b[nt], st + offB[ks][nt]);
#pragma unroll
            for (int mt = 0; mt < 2; mt++)
#pragma unroll
                for (int f = 0; f < 8; f++)
                    mma16816(acc[mt][f], a[mt], &b[f >> 1][(f & 1) * 2]);
        }
    }

    // --- epilogue ---
    int mrow = lane >> 2, ncol = (lane & 3) * 2;
#pragma unroll
    for (int mt = 0; mt < 2; mt++) {
#pragma unroll
        for (int h = 0; h < 2; h++) {
            int row = row0 + wm + mt * 16 + h * 8 + mrow;
            size_t rb = (size_t)row * N;
#pragma unroll
            for (int nt = 0; nt < 8; nt++) {
                int col = col0 + wn + nt * 8 + ncol;
                float vx = acc[mt][nt][h * 2 + 0];
                float vy = acc[mt][nt][h * 2 + 1];
                if (BIAS) { vx += bias[col]; vy += bias[col + 1]; }
                if (RES) {
                    float2 rv = *(const float2*)(res + rb + col);
                    vx += rv.x; vy += rv.y;
                }
                if (sizeof(OutT) == 2) {
                    *(__half2*)((__half*)C + rb + col) = __floats2half2_rn(vx, vy);
                } else {
                    float2 v; v.x = vx; v.y = vy;
                    *(float2*)((float*)C + rb + col) = v;
                }
            }
        }
    }
}

// ---------------------------------------------------------------------------
// Weight transpose + fp16 convert: W[K,N] fp32 -> T[N,K] fp16
// ---------------------------------------------------------------------------
__global__ void wsplit(const float* __restrict__ W, __half* __restrict__ T,
                       int K, int N, int rowOff)
{
    __shared__ float tile[32][33];
    int n0 = blockIdx.x * 32, k0 = blockIdx.y * 32;
    int tx = threadIdx.x, ty = threadIdx.y;
    for (int j = ty; j < 32; j += 8)
        tile[j][tx] = W[(size_t)(k0 + j) * N + n0 + tx];
    __syncthreads();
    for (int j = ty; j < 32; j += 8) {
        float v = tile[tx][j];
        T[(size_t)(rowOff + n0 + j) * K + k0 + tx] = __float2half_rn(v);
    }
}

// ---------------------------------------------------------------------------
// LayerNorm -> fp16
// ---------------------------------------------------------------------------
__global__ __launch_bounds__(256) void ln_h(
    const float* __restrict__ in, const float* __restrict__ gamma,
    const float* __restrict__ beta, __half* __restrict__ oh)
{
    int row = blockIdx.x;
    const float4* inr = (const float4*)(in + (size_t)row * DIM);
    float4 xv = inr[threadIdx.x];

    float s  = xv.x + xv.y + xv.z + xv.w;
    float ss = xv.x * xv.x + xv.y * xv.y + xv.z * xv.z + xv.w * xv.w;
#pragma unroll
    for (int o = 16; o > 0; o >>= 1) {
        s  += __shfl_down_sync(0xffffffff, s,  o);
        ss += __shfl_down_sync(0xffffffff, ss, o);
    }
    __shared__ float rs[8], rss[8];
    __shared__ float s_mean, s_rstd;
    int warp = threadIdx.x >> 5, lane = threadIdx.x & 31;
    if (lane == 0) { rs[warp] = s; rss[warp] = ss; }
    __syncthreads();
    if (threadIdx.x == 0) {
        float t = 0.f, t2 = 0.f;
#pragma unroll
        for (int i = 0; i < 8; i++) { t += rs[i]; t2 += rss[i]; }
        float m = t / (float)DIM;
        s_mean = m;
        s_rstd = rsqrtf(t2 / (float)DIM - m * m + LN_EPS);
    }
    __syncthreads();
    float m = s_mean, r = s_rstd;

    float4 gv = ((const float4*)gamma)[threadIdx.x];
    float4 bv = ((const float4*)beta)[threadIdx.x];
    float o0 = (xv.x - m) * r * gv.x + bv.x;
    float o1 = (xv.y - m) * r * gv.y + bv.y;
    float o2 = (xv.z - m) * r * gv.z + bv.z;
    float o3 = (xv.w - m) * r * gv.w + bv.w;

    size_t ob = (size_t)row * DIM + threadIdx.x * 4;
    *(__half2*)(oh + ob)     = __floats2half2_rn(o0, o1);
    *(__half2*)(oh + ob + 2) = __floats2half2_rn(o2, o3);
}

// ---------------------------------------------------------------------------
// Sliding-window causal local attention (fp16 qkv in, fp32 math, fp16 out)
// ---------------------------------------------------------------------------
#define ACHUNK 64
__global__ __launch_bounds__(128) void attn_kernel(
    const __half* __restrict__ QKV, const float* __restrict__ relb,
    __half* __restrict__ Oh)
{
    __shared__ float sK[ACHUNK][HEAD_DIM];
    __shared__ float sV[ACHUNK][HEAD_DIM];

    int n = blockIdx.x, h = blockIdx.y, b = blockIdx.z;
    int i = threadIdx.x;

    size_t rowq = (size_t)(b * SEQ + n * WIN + i);
    float q[HEAD_DIM];
    {
        const __half2* qp = (const __half2*)(QKV + rowq * 3072 + h * HEAD_DIM);
#pragma unroll
        for (int c = 0; c < HEAD_DIM / 2; c++) {
            float2 t = __half22float2(qp[c]);
            q[2 * c + 0] = t.x; q[2 * c + 1] = t.y;
        }
    }

    float mmax = -1e30f, lsum = 0.f;
    float acc[HEAD_DIM];
#pragma unroll
    for (int d = 0; d < HEAD_DIM; d++) acc[d] = 0.f;

    const float* biasrow = relb + h * (2 * WIN);

    for (int c = 0; c < 2 * WIN / ACHUNK; c++) {
        if (n == 0 && c < WIN / ACHUNK) continue;
        int j0 = c * ACHUNK;
        int pos0 = (n - 1) * WIN + j0;

        __syncthreads();
        // cooperative load: 64 rows x 8 chunks (8 halves each) for K and V
        for (int t = i; t < ACHUNK * 8; t += 128) {
            int r = t >> 3, cc = t & 7;
            size_t rk = (size_t)(b * SEQ + pos0 + r) * 3072 + h * HEAD_DIM + cc * 8;
            const __half2* kp = (const __half2*)(QKV + rk + 1024);
            const __half2* vp = (const __half2*)(QKV + rk + 2048);
#pragma unroll
            for (int u = 0; u < 4; u++) {
                float2 kf = __half22float2(kp[u]);
                float2 vf = __half22float2(vp[u]);
                sK[r][cc * 8 + 2 * u]     = kf.x;
                sK[r][cc * 8 + 2 * u + 1] = kf.y;
                sV[r][cc * 8 + 2 * u]     = vf.x;
                sV[r][cc * 8 + 2 * u + 1] = vf.y;
            }
        }
        __syncthreads();

        int jmax = i + WIN - j0 + 1;
        if (jmax > ACHUNK) jmax = ACHUNK;
        for (int jj = 0; jj < jmax; jj++) {
            float s = 0.f;
#pragma unroll
            for (int d = 0; d < HEAD_DIM; d++) s = fmaf(q[d], sK[jj][d], s);
            int dist = i + WIN - (j0 + jj);
            s = s * 0.125f + biasrow[dist];

            float mnew = fmaxf(mmax, s);
            float cf = __expf(mmax - mnew);
            float p  = __expf(s - mnew);
            lsum = lsum * cf + p;
#pragma unroll
            for (int d = 0; d < HEAD_DIM; d++)
                acc[d] = fmaf(p, sV[jj][d], acc[d] * cf);
            mmax = mnew;
        }
    }

    float inv = 1.f / lsum;
    size_t ob = rowq * DIM + h * HEAD_DIM;
#pragma unroll
    for (int d = 0; d < HEAD_DIM; d += 2)
        *(__half2*)(Oh + ob + d) = __floats2half2_rn(acc[d] * inv, acc[d + 1] * inv);
}

// ---------------------------------------------------------------------------
// GEGLU: h = val * gelu_exact(gate), fp16 in/out, fp32 math (8 elems/thread)
// ---------------------------------------------------------------------------
__global__ __launch_bounds__(256) void geglu_h(
    const __half* __restrict__ proj, __half* __restrict__ oh)
{
    size_t t8 = ((size_t)blockIdx.x * 256 + threadIdx.x) * 8;   // over ROWS*HIDDEN
    size_t row = t8 / HIDDEN;
    int c = (int)(t8 - row * HIDDEN);
    const __half2* vp = (const __half2*)(proj + row * 4096 + c);
    const __half2* gp = (const __half2*)(proj + row * 4096 + 2048 + c);

    __half2 o[4];
#pragma unroll
    for (int u = 0; u < 4; u++) {
        float2 vf = __half22float2(vp[u]);
        float2 gf = __half22float2(gp[u]);
        float g0 = 0.5f * gf.x * (1.f + erff(gf.x * 0.70710678118654752440f));
        float g1 = 0.5f * gf.y * (1.f + erff(gf.y * 0.70710678118654752440f));
        o[u] = __floats2half2_rn(vf.x * g0, vf.y * g1);
    }
    *(uint2*)(oh + t8)     = *(uint2*)&o[0];
    *(uint2*)(oh + t8 + 4) = *(uint2*)&o[2];
}

// ---------------------------------------------------------------------------
// Launch
// ---------------------------------------------------------------------------
extern "C" void kernel_launch(void* const* d_in, const int* in_sizes, int n_in,
                              void* d_out, int out_size)
{
    const float* x      = (const float*)d_in[0];
    const float* ln1_g  = (const float*)d_in[1];
    const float* ln1_b  = (const float*)d_in[2];
    const float* ln2_g  = (const float*)d_in[3];
    const float* ln2_b  = (const float*)d_in[4];
    const float* wq     = (const float*)d_in[5];
    const float* wk     = (const float*)d_in[6];
    const float* wv     = (const float*)d_in[7];
    const float* wo     = (const float*)d_in[8];
    const float* bo     = (const float*)d_in[9];
    const float* relb   = (const float*)d_in[10];
    const float* w_ff1  = (const float*)d_in[11];
    const float* b_ff1  = (const float*)d_in[12];
    const float* w_ff2  = (const float*)d_in[13];
    const float* b_ff2  = (const float*)d_in[14];
    float* out = (float*)d_out;

    __half *act, *qkv, *proj, *wqkvh, *woh, *f1h, *f2h;
    float *x1;
    cudaGetSymbolAddress((void**)&act,  g_act);
    cudaGetSymbolAddress((void**)&qkv,  g_qkv);
    cudaGetSymbolAddress((void**)&x1,   g_x1);
    cudaGetSymbolAddress((void**)&proj, g_proj);
    cudaGetSymbolAddress((void**)&wqkvh, g_wqkv);
    cudaGetSymbolAddress((void**)&woh,  g_wo);
    cudaGetSymbolAddress((void**)&f1h,  g_ff1);
    cudaGetSymbolAddress((void**)&f2h,  g_ff2);

    cudaFuncSetAttribute(gemm_mma<false, false, __half>, cudaFuncAttributeMaxDynamicSharedMemorySize, GEMM_SMEM);
    cudaFuncSetAttribute(gemm_mma<true,  false, __half>, cudaFuncAttributeMaxDynamicSharedMemorySize, GEMM_SMEM);
    cudaFuncSetAttribute(gemm_mma<true,  true,  float>,  cudaFuncAttributeMaxDynamicSharedMemorySize, GEMM_SMEM);

    dim3 tb(32, 8);
    wsplit<<<dim3(32, 32), tb>>>(wq,    wqkvh, 1024, 1024, 0);
    wsplit<<<dim3(32, 32), tb>>>(wk,    wqkvh, 1024, 1024, 1024);
    wsplit<<<dim3(32, 32), tb>>>(wv,    wqkvh, 1024, 1024, 2048);
    wsplit<<<dim3(32, 32), tb>>>(wo,    woh,   1024, 1024, 0);
    wsplit<<<dim3(128, 32), tb>>>(w_ff1, f1h,  1024, 4096, 0);
    wsplit<<<dim3(32, 64), tb>>>(w_ff2, f2h,   2048, 1024, 0);

    // 1. ln1(x) -> act
    ln_h<<<ROWS, 256>>>(x, ln1_g, ln1_b, act);
    // 2. qkv = ln @ [wq|wk|wv]  (fp16 out)
    gemm_mma<false, false, __half><<<dim3(3072 / BN, ROWS / BM), 256, GEMM_SMEM>>>(
        act, wqkvh, nullptr, nullptr, qkv, 1024, 3072);
    // 3. attention -> act (fp16)
    attn_kernel<<<dim3(NWIN, HEADS, BATCH), 128>>>(qkv, relb, act);
    // 4. x1 = attn @ wo + bo + x  (fp32 out)
    gemm_mma<true, true, float><<<dim3(1024 / BN, ROWS / BM), 256, GEMM_SMEM>>>(
        act, woh, bo, x, x1, 1024, 1024);
    // 5. ln2(x1) -> act
    ln_h<<<ROWS, 256>>>(x1, ln2_g, ln2_b, act);
    // 6. proj = ln2 @ w_ff1 + b_ff1  (fp16 out)
    gemm_mma<true, false, __half><<<dim3(4096 / BN, ROWS / BM), 256, GEMM_SMEM>>>(
        act, f1h, b_ff1, nullptr, proj, 1024, 4096);
    // 7. geglu -> act
    geglu_h<<<(ROWS * HIDDEN) / 2048, 256>>>(proj, act);
    // 8. out = h @ w_ff2 + b_ff2 + x1  (fp32 out)
    gemm_mma<true, true, float><<<dim3(1024 / BN, ROWS / BM), 256, GEMM_SMEM>>>(
        act, f2h, b_ff2, x1, out, 2048, 1024);
}

// round 6
// speedup vs baseline: 5.8588x; 1.4050x over previous
#include <cuda_runtime.h>
#include <cuda_fp16.h>
#include <cstdint>
#include <math.h>

#define BATCH 4
#define SEQ 4096
#define DIM 1024
#define HEADS 16
#define HEAD_DIM 64
#define WIN 128
#define NWIN 32
#define HIDDEN 2048
#define ROWS 16384
#define LN_EPS 1e-5f
#define RSQRT2 0.70710678118654752440f

// ---------------------------------------------------------------------------
// Scratch buffers
// ---------------------------------------------------------------------------
__device__ __align__(256) __half g_act[(size_t)ROWS * 2048];
__device__ __align__(256) __half g_qkv[(size_t)ROWS * 3072];   // also geglu out
__device__ __align__(256) float  g_x1[(size_t)ROWS * DIM];
__device__ __align__(256) __half g_wqkv[3072 * 1024];
__device__ __align__(256) __half g_wo[1024 * 1024];
__device__ __align__(256) __half g_ff1[4096 * 1024];
__device__ __align__(256) __half g_ff2[1024 * 2048];

// ---------------------------------------------------------------------------
// PTX helpers (baseline sm_80-class PTX)
// ---------------------------------------------------------------------------
__device__ __forceinline__ uint32_t smem_to_u32(const void* p) {
    uint32_t a;
    asm("{ .reg .u64 t; cvta.to.shared.u64 t, %1; cvt.u32.u64 %0, t; }" : "=r"(a) : "l"(p));
    return a;
}
__device__ __forceinline__ void cp16(uint32_t dst, const void* src) {
    asm volatile("cp.async.cg.shared.global [%0], [%1], 16;" :: "r"(dst), "l"(src));
}
__device__ __forceinline__ void ldsm4(uint32_t* r, uint32_t addr) {
    asm volatile("ldmatrix.sync.aligned.m8n8.x4.shared.b16 {%0,%1,%2,%3}, [%4];"
        : "=r"(r[0]), "=r"(r[1]), "=r"(r[2]), "=r"(r[3]) : "r"(addr));
}
__device__ __forceinline__ void ldsm4t(uint32_t* r, uint32_t addr) {
    asm volatile("ldmatrix.sync.aligned.m8n8.x4.trans.shared.b16 {%0,%1,%2,%3}, [%4];"
        : "=r"(r[0]), "=r"(r[1]), "=r"(r[2]), "=r"(r[3]) : "r"(addr));
}
__device__ __forceinline__ void mma16816(float* c, const uint32_t* a, const uint32_t* b) {
    asm volatile(
        "mma.sync.aligned.m16n8k16.row.col.f32.f16.f16.f32 "
        "{%0,%1,%2,%3}, {%4,%5,%6,%7}, {%8,%9}, {%0,%1,%2,%3};"
        : "+f"(c[0]), "+f"(c[1]), "+f"(c[2]), "+f"(c[3])
        : "r"(a[0]), "r"(a[1]), "r"(a[2]), "r"(a[3]), "r"(b[0]), "r"(b[1]));
}
__device__ __forceinline__ uint32_t h2u(__half2 v) { return *(uint32_t*)&v; }

// ---------------------------------------------------------------------------
// GEMM: C = A @ B^T, fp16 ops, fp32 acc. EPI: 0=half out; 1=+bias half out;
// 2=+bias+res float out; 3=geglu (interleaved val/gate cols -> half out N/2)
// ---------------------------------------------------------------------------
#define BM 128
#define BN 128
#define BK 32
#define STG_BYTES 16384
#define NSTAGE 4
#define GEMM_SMEM (NSTAGE * STG_BYTES)

template <int EPI>
__global__ __launch_bounds__(256, 2) void gemm_mma(
    const __half* __restrict__ Ag, const __half* __restrict__ Bg,
    const float* __restrict__ bias, const float* __restrict__ res,
    void* __restrict__ Cv, int K, int N)
{
    extern __shared__ __align__(1024) char smem[];
    uint32_t sb = smem_to_u32(smem);
    int tid = threadIdx.x, lane = tid & 31, wid = tid >> 5;
    int row0 = blockIdx.y * BM, col0 = blockIdx.x * BN;
    int wm = (wid & 3) * 32, wn = (wid >> 2) * 64;
    int total = K / BK;

    uint32_t dA[2], dB[2];
    size_t sAo[2], sBo[2];
#pragma unroll
    for (int i = 0; i < 2; i++) {
        int cid = tid + i * 256;
        int r = cid >> 2, c = cid & 3;
        uint32_t off = (uint32_t)(r * 64 + ((c ^ (r & 3)) << 4));
        dA[i] = off;
        dB[i] = 8192u + off;
        sAo[i] = (size_t)(row0 + r) * K + c * 8;
        sBo[i] = (size_t)(col0 + r) * K + c * 8;
    }

    auto load_stage = [&](int kv, int s) {
        int k0 = kv * BK;
        uint32_t st = sb + (uint32_t)s * STG_BYTES;
#pragma unroll
        for (int i = 0; i < 2; i++) {
            cp16(st + dA[i], Ag + sAo[i] + k0);
            cp16(st + dB[i], Bg + sBo[i] + k0);
        }
        asm volatile("cp.async.commit_group;" ::: "memory");
    };

    uint32_t offA[2][2], offB[2][4];
#pragma unroll
    for (int ks = 0; ks < 2; ks++) {
#pragma unroll
        for (int mt = 0; mt < 2; mt++) {
            int r = wm + mt * 16 + (lane & 15);
            int c = ks * 2 + (lane >> 4);
            offA[ks][mt] = (uint32_t)(r * 64 + ((c ^ (r & 3)) << 4));
        }
#pragma unroll
        for (int nt = 0; nt < 4; nt++) {
            int r = wn + nt * 16 + (lane & 7) + ((lane & 16) >> 1);
            int c = ks * 2 + ((lane >> 3) & 1);
            offB[ks][nt] = (uint32_t)(8192 + r * 64 + ((c ^ (r & 3)) << 4));
        }
    }

    float acc[2][8][4];
#pragma unroll
    for (int mt = 0; mt < 2; mt++)
#pragma unroll
        for (int f = 0; f < 8; f++)
#pragma unroll
            for (int j = 0; j < 4; j++) acc[mt][f][j] = 0.f;

    load_stage(0, 0);
    load_stage(1, 1);
    load_stage(2, 2);

    for (int kv = 0; kv < total; kv++) {
        if (kv < total - 2)
            asm volatile("cp.async.wait_group 2;" ::: "memory");
        else if (kv == total - 2)
            asm volatile("cp.async.wait_group 1;" ::: "memory");
        else
            asm volatile("cp.async.wait_group 0;" ::: "memory");
        __syncthreads();
        if (kv + 3 < total) load_stage(kv + 3, (kv + 3) % NSTAGE);

        uint32_t st = sb + (uint32_t)(kv % NSTAGE) * STG_BYTES;
#pragma unroll
        for (int ks = 0; ks < 2; ks++) {
            uint32_t a[2][4], b[4][4];
#pragma unroll
            for (int mt = 0; mt < 2; mt++) ldsm4(a[mt], st + offA[ks][mt]);
#pragma unroll
            for (int nt = 0; nt < 4; nt++) ldsm4(b[nt], st + offB[ks][nt]);
#pragma unroll
            for (int mt = 0; mt < 2; mt++)
#pragma unroll
                for (int f = 0; f < 8; f++)
                    mma16816(acc[mt][f], a[mt], &b[f >> 1][(f & 1) * 2]);
        }
    }

    int mrow = lane >> 2, ncol = (lane & 3) * 2;
#pragma unroll
    for (int mt = 0; mt < 2; mt++) {
#pragma unroll
        for (int h = 0; h < 2; h++) {
            int row = row0 + wm + mt * 16 + h * 8 + mrow;
#pragma unroll
            for (int nt = 0; nt < 8; nt++) {
                int col = col0 + wn + nt * 8 + ncol;
                float vx = acc[mt][nt][h * 2 + 0];
                float vy = acc[mt][nt][h * 2 + 1];
                if (EPI == 0) {
                    *(__half2*)((__half*)Cv + (size_t)row * N + col) =
                        __floats2half2_rn(vx, vy);
                } else if (EPI == 1) {
                    vx += bias[col]; vy += bias[col + 1];
                    *(__half2*)((__half*)Cv + (size_t)row * N + col) =
                        __floats2half2_rn(vx, vy);
                } else if (EPI == 2) {
                    size_t rb = (size_t)row * N;
                    vx += bias[col]; vy += bias[col + 1];
                    float2 rv = *(const float2*)(res + rb + col);
                    float2 v; v.x = vx + rv.x; v.y = vy + rv.y;
                    *(float2*)((float*)Cv + rb + col) = v;
                } else {  // EPI 3: geglu, interleaved (val,gate) pairs
                    int p = col >> 1;
                    float val  = vx + bias[p];
                    float gate = vy + bias[2048 + p];
                    float ge = 0.5f * gate * (1.f + erff(gate * RSQRT2));
                    ((__half*)Cv)[(size_t)row * 2048 + p] = __float2half_rn(val * ge);
                }
            }
        }
    }
}

// ---------------------------------------------------------------------------
// Weight transpose + fp16 convert: W[K,N] fp32 -> T[N,K] fp16
// ---------------------------------------------------------------------------
__global__ void wsplit(const float* __restrict__ W, __half* __restrict__ T,
                       int K, int N, int rowOff)
{
    __shared__ float tile[32][33];
    int n0 = blockIdx.x * 32, k0 = blockIdx.y * 32;
    int tx = threadIdx.x, ty = threadIdx.y;
    for (int j = ty; j < 32; j += 8)
        tile[j][tx] = W[(size_t)(k0 + j) * N + n0 + tx];
    __syncthreads();
    for (int j = ty; j < 32; j += 8)
        T[(size_t)(rowOff + n0 + j) * K + k0 + tx] = __float2half_rn(tile[tx][j]);
}

// FF1 with val/gate column interleave: orig col c<2048 -> row 2c; c>=2048 -> 2(c-2048)+1
__global__ void wsplit_ff1(const float* __restrict__ W, __half* __restrict__ T)
{
    __shared__ float tile[32][33];
    int n0 = blockIdx.x * 32, k0 = blockIdx.y * 32;
    int tx = threadIdx.x, ty = threadIdx.y;
    for (int j = ty; j < 32; j += 8)
        tile[j][tx] = W[(size_t)(k0 + j) * 4096 + n0 + tx];
    __syncthreads();
    for (int j = ty; j < 32; j += 8) {
        int col = n0 + j;
        int nr = (col < 2048) ? (2 * col) : (2 * (col - 2048) + 1);
        T[(size_t)nr * 1024 + k0 + tx] = __float2half_rn(tile[tx][j]);
    }
}

// ---------------------------------------------------------------------------
// LayerNorm -> fp16
// ---------------------------------------------------------------------------
__global__ __launch_bounds__(256) void ln_h(
    const float* __restrict__ in, const float* __restrict__ gamma,
    const float* __restrict__ beta, __half* __restrict__ oh)
{
    int row = blockIdx.x;
    const float4* inr = (const float4*)(in + (size_t)row * DIM);
    float4 xv = inr[threadIdx.x];

    float s  = xv.x + xv.y + xv.z + xv.w;
    float ss = xv.x * xv.x + xv.y * xv.y + xv.z * xv.z + xv.w * xv.w;
#pragma unroll
    for (int o = 16; o > 0; o >>= 1) {
        s  += __shfl_down_sync(0xffffffff, s,  o);
        ss += __shfl_down_sync(0xffffffff, ss, o);
    }
    __shared__ float rs[8], rss[8];
    __shared__ float s_mean, s_rstd;
    int warp = threadIdx.x >> 5, lane = threadIdx.x & 31;
    if (lane == 0) { rs[warp] = s; rss[warp] = ss; }
    __syncthreads();
    if (threadIdx.x == 0) {
        float t = 0.f, t2 = 0.f;
#pragma unroll
        for (int i = 0; i < 8; i++) { t += rs[i]; t2 += rss[i]; }
        float m = t / (float)DIM;
        s_mean = m;
        s_rstd = rsqrtf(t2 / (float)DIM - m * m + LN_EPS);
    }
    __syncthreads();
    float m = s_mean, r = s_rstd;

    float4 gv = ((const float4*)gamma)[threadIdx.x];
    float4 bv = ((const float4*)beta)[threadIdx.x];
    float o0 = (xv.x - m) * r * gv.x + bv.x;
    float o1 = (xv.y - m) * r * gv.y + bv.y;
    float o2 = (xv.z - m) * r * gv.z + bv.z;
    float o3 = (xv.w - m) * r * gv.w + bv.w;

    size_t ob = (size_t)row * DIM + threadIdx.x * 4;
    *(__half2*)(oh + ob)     = __floats2half2_rn(o0, o1);
    *(__half2*)(oh + ob + 2) = __floats2half2_rn(o2, o3);
}

// ---------------------------------------------------------------------------
// Flash attention via mma.sync. One block per (window, head, batch),
// 128 threads (4 warps x 32 Q rows). Whole Q[128,64] + K/V[256,64] in smem.
// ---------------------------------------------------------------------------
#define SQ_OFF 0
#define SK_OFF 16384
#define SV_OFF 49152
#define SB_OFF 81920
#define ATT_SMEM (SB_OFF + 1024)

__device__ __forceinline__ uint32_t swzoff(int r, int cc) {
    return (uint32_t)(r * 128 + ((cc ^ (r & 7)) << 4));
}

__global__ __launch_bounds__(128) void attn_mma(
    const __half* __restrict__ QKV, const float* __restrict__ relb,
    __half* __restrict__ Oh)
{
    extern __shared__ __align__(1024) char sm[];
    uint32_t sb = smem_to_u32(sm);
    float* sBias = (float*)(sm + SB_OFF);

    int n = blockIdx.x, h = blockIdx.y, b = blockIdx.z;
    int tid = threadIdx.x, lane = tid & 31, wid = tid >> 5;

    // ---- stage Q, K, V, bias ----
    size_t qbase = ((size_t)(b * SEQ + n * WIN)) * 3072 + h * 64;
    size_t kvbase = ((size_t)(b * SEQ + (n - 1) * WIN)) * 3072 + h * 64;
#pragma unroll
    for (int i = 0; i < 8; i++) {
        int id = tid + i * 128, r = id >> 3, cc = id & 7;
        cp16(sb + SQ_OFF + swzoff(r, cc), QKV + qbase + (size_t)r * 3072 + cc * 8);
    }
#pragma unroll
    for (int i = 0; i < 16; i++) {
        int id = tid + i * 128, r = id >> 3, cc = id & 7;
        if (n > 0 || r >= 128) {
            cp16(sb + SK_OFF + swzoff(r, cc), QKV + kvbase + (size_t)r * 3072 + 1024 + cc * 8);
            cp16(sb + SV_OFF + swzoff(r, cc), QKV + kvbase + (size_t)r * 3072 + 2048 + cc * 8);
        }
    }
    sBias[tid]       = relb[h * 256 + tid];
    sBias[tid + 128] = relb[h * 256 + 128 + tid];
    asm volatile("cp.async.commit_group;" ::: "memory");
    asm volatile("cp.async.wait_group 0;" ::: "memory");
    __syncthreads();

    // ---- Q fragments (persist across KV chunks) ----
    uint32_t qf[2][4][4];
#pragma unroll
    for (int mt = 0; mt < 2; mt++)
#pragma unroll
        for (int kk = 0; kk < 4; kk++) {
            int r = wid * 32 + mt * 16 + (lane & 15);
            int cc = kk * 2 + (lane >> 4);
            ldsm4(qf[mt][kk], sb + SQ_OFF + swzoff(r, cc));
        }

    float m[2][2], l[2][2], oacc[2][8][4];
#pragma unroll
    for (int mt = 0; mt < 2; mt++)
#pragma unroll
        for (int hh = 0; hh < 2; hh++) { m[mt][hh] = -1e30f; l[mt][hh] = 0.f; }
#pragma unroll
    for (int mt = 0; mt < 2; mt++)
#pragma unroll
        for (int f = 0; f < 8; f++)
#pragma unroll
            for (int j = 0; j < 4; j++) oacc[mt][f][j] = 0.f;

    int cstart = (n == 0) ? 2 : 0;
    for (int c = cstart; c < 4; c++) {
        int j0 = c * 64;

        // ---- S = Q K^T ----
        float sacc[2][8][4];
#pragma unroll
        for (int mt = 0; mt < 2; mt++)
#pragma unroll
            for (int f = 0; f < 8; f++)
#pragma unroll
                for (int j = 0; j < 4; j++) sacc[mt][f][j] = 0.f;

#pragma unroll
        for (int kk = 0; kk < 4; kk++) {
            uint32_t kb[4][4];
#pragma unroll
            for (int nt2 = 0; nt2 < 4; nt2++) {
                int r = j0 + nt2 * 16 + (lane & 7) + ((lane & 16) >> 1);
                int cc = kk * 2 + ((lane >> 3) & 1);
                ldsm4(kb[nt2], sb + SK_OFF + swzoff(r, cc));
            }
#pragma unroll
            for (int mt = 0; mt < 2; mt++)
#pragma unroll
                for (int nt2 = 0; nt2 < 4; nt2++) {
                    mma16816(sacc[mt][2 * nt2],     qf[mt][kk], &kb[nt2][0]);
                    mma16816(sacc[mt][2 * nt2 + 1], qf[mt][kk], &kb[nt2][2]);
                }
        }

        // ---- online softmax + pack P into A-fragments ----
        uint32_t pf[2][4][4];
#pragma unroll
        for (int mt = 0; mt < 2; mt++) {
#pragma unroll
            for (int hh = 0; hh < 2; hh++) {
                int i = wid * 32 + mt * 16 + hh * 8 + (lane >> 2);
                float sv[16], mx = -1e30f;
#pragma unroll
                for (int nt = 0; nt < 8; nt++) {
#pragma unroll
                    for (int e = 0; e < 2; e++) {
                        int j = j0 + nt * 8 + (lane & 3) * 2 + e;
                        int dist = i + 128 - j;
                        int db = dist < 0 ? 0 : dist;
                        float s = (dist >= 0)
                            ? sacc[mt][nt][hh * 2 + e] * 0.125f + sBias[db]
                            : -1e9f;
                        sv[nt * 2 + e] = s;
                        mx = fmaxf(mx, s);
                    }
                }
                mx = fmaxf(mx, __shfl_xor_sync(0xffffffff, mx, 1));
                mx = fmaxf(mx, __shfl_xor_sync(0xffffffff, mx, 2));
                float mnew = fmaxf(m[mt][hh], mx);
                float cf = __expf(m[mt][hh] - mnew);
                float rs = 0.f;
#pragma unroll
                for (int t = 0; t < 16; t++) {
                    sv[t] = __expf(sv[t] - mnew);
                    rs += sv[t];
                }
                rs += __shfl_xor_sync(0xffffffff, rs, 1);
                rs += __shfl_xor_sync(0xffffffff, rs, 2);
                l[mt][hh] = l[mt][hh] * cf + rs;
                m[mt][hh] = mnew;
#pragma unroll
                for (int nt = 0; nt < 8; nt++) {
                    oacc[mt][nt][hh * 2]     *= cf;
                    oacc[mt][nt][hh * 2 + 1] *= cf;
                }
#pragma unroll
                for (int kk2 = 0; kk2 < 4; kk2++) {
                    pf[mt][kk2][hh]     = h2u(__floats2half2_rn(sv[4 * kk2],     sv[4 * kk2 + 1]));
                    pf[mt][kk2][2 + hh] = h2u(__floats2half2_rn(sv[4 * kk2 + 2], sv[4 * kk2 + 3]));
                }
            }
        }

        // ---- O += P V ----
#pragma unroll
        for (int kk2 = 0; kk2 < 4; kk2++) {
            uint32_t vb[4][4];
#pragma unroll
            for (int d16 = 0; d16 < 4; d16++) {
                int r = j0 + kk2 * 16 + (lane & 15);
                int cc = d16 * 2 + (lane >> 4);
                ldsm4t(vb[d16], sb + SV_OFF + swzoff(r, cc));
            }
#pragma unroll
            for (int mt = 0; mt < 2; mt++)
#pragma unroll
                for (int d16 = 0; d16 < 4; d16++) {
                    mma16816(oacc[mt][2 * d16],     pf[mt][kk2], &vb[d16][0]);
                    mma16816(oacc[mt][2 * d16 + 1], pf[mt][kk2], &vb[d16][2]);
                }
        }
    }

    // ---- normalize + write ----
#pragma unroll
    for (int mt = 0; mt < 2; mt++) {
#pragma unroll
        for (int hh = 0; hh < 2; hh++) {
            float inv = 1.f / l[mt][hh];
            size_t row = (size_t)(b * SEQ + n * WIN + wid * 32 + mt * 16 + hh * 8 + (lane >> 2));
            size_t ob = row * 1024 + h * 64;
#pragma unroll
            for (int nt = 0; nt < 8; nt++) {
                int col = nt * 8 + (lane & 3) * 2;
                *(__half2*)(Oh + ob + col) = __floats2half2_rn(
                    oacc[mt][nt][hh * 2] * inv, oacc[mt][nt][hh * 2 + 1] * inv);
            }
        }
    }
}

// ---------------------------------------------------------------------------
// Launch
// ---------------------------------------------------------------------------
extern "C" void kernel_launch(void* const* d_in, const int* in_sizes, int n_in,
                              void* d_out, int out_size)
{
    const float* x      = (const float*)d_in[0];
    const float* ln1_g  = (const float*)d_in[1];
    const float* ln1_b  = (const float*)d_in[2];
    const float* ln2_g  = (const float*)d_in[3];
    const float* ln2_b  = (const float*)d_in[4];
    const float* wq     = (const float*)d_in[5];
    const float* wk     = (const float*)d_in[6];
    const float* wv     = (const float*)d_in[7];
    const float* wo     = (const float*)d_in[8];
    const float* bo     = (const float*)d_in[9];
    const float* relb   = (const float*)d_in[10];
    const float* w_ff1  = (const float*)d_in[11];
    const float* b_ff1  = (const float*)d_in[12];
    const float* w_ff2  = (const float*)d_in[13];
    const float* b_ff2  = (const float*)d_in[14];
    float* out = (float*)d_out;

    __half *act, *qkv, *wqkvh, *woh, *f1h, *f2h;
    float *x1;
    cudaGetSymbolAddress((void**)&act,  g_act);
    cudaGetSymbolAddress((void**)&qkv,  g_qkv);
    cudaGetSymbolAddress((void**)&x1,   g_x1);
    cudaGetSymbolAddress((void**)&wqkvh, g_wqkv);
    cudaGetSymbolAddress((void**)&woh,  g_wo);
    cudaGetSymbolAddress((void**)&f1h,  g_ff1);
    cudaGetSymbolAddress((void**)&f2h,  g_ff2);

    cudaFuncSetAttribute(gemm_mma<0>, cudaFuncAttributeMaxDynamicSharedMemorySize, GEMM_SMEM);
    cudaFuncSetAttribute(gemm_mma<2>, cudaFuncAttributeMaxDynamicSharedMemorySize, GEMM_SMEM);
    cudaFuncSetAttribute(gemm_mma<3>, cudaFuncAttributeMaxDynamicSharedMemorySize, GEMM_SMEM);
    cudaFuncSetAttribute(attn_mma,    cudaFuncAttributeMaxDynamicSharedMemorySize, ATT_SMEM);

    dim3 tb(32, 8);
    // launch idx 0..4 (ncu -s 5 -c 1 captures idx 5 = QKV GEMM)
    wsplit<<<dim3(32, 32), tb>>>(wq, wqkvh, 1024, 1024, 0);
    wsplit<<<dim3(32, 32), tb>>>(wk, wqkvh, 1024, 1024, 1024);
    wsplit<<<dim3(32, 32), tb>>>(wv, wqkvh, 1024, 1024, 2048);
    wsplit<<<dim3(32, 32), tb>>>(wo, woh,   1024, 1024, 0);
    ln_h<<<ROWS, 256>>>(x, ln1_g, ln1_b, act);
    // idx 5: qkv = ln1 @ [wq|wk|wv]
    gemm_mma<0><<<dim3(3072 / BN, ROWS / BM), 256, GEMM_SMEM>>>(
        act, wqkvh, nullptr, nullptr, qkv, 1024, 3072);
    // idx 6: attention (tensor-core flash) -> act
    attn_mma<<<dim3(NWIN, HEADS, BATCH), 128, ATT_SMEM>>>(qkv, relb, act);
    // idx 7: x1 = attn @ wo + bo + x
    gemm_mma<2><<<dim3(1024 / BN, ROWS / BM), 256, GEMM_SMEM>>>(
        act, woh, bo, x, x1, 1024, 1024);
    // idx 8: ln2 -> act
    ln_h<<<ROWS, 256>>>(x1, ln2_g, ln2_b, act);
    // idx 9,10: FF weight prep
    wsplit_ff1<<<dim3(128, 32), tb>>>(w_ff1, f1h);
    wsplit<<<dim3(32, 64), tb>>>(w_ff2, f2h, 2048, 1024, 0);
    // idx 11: fused FF1 + GEGLU: act (A) -> qkv (out, [ROWS,2048] fp16) — NO aliasing
    gemm_mma<3><<<dim3(4096 / BN, ROWS / BM), 256, GEMM_SMEM>>>(
        act, f1h, b_ff1, nullptr, qkv, 1024, 4096);
    // idx 12: out = geglu @ w_ff2 + b_ff2 + x1
    gemm_mma<2><<<dim3(1024 / BN, ROWS / BM), 256, GEMM_SMEM>>>(
        qkv, f2h, b_ff2, x1, out, 2048, 1024);
}